// round 12
// baseline (speedup 1.0000x reference)
#include <cuda_runtime.h>
#include <cuda_bf16.h>
#include <math.h>

// ModalSynth: y[b,0,j] = sum_m a[b,m,j] * sin( cumsum_j(w[b,m,:]) + phase0[b,m] )
// params: (16, 3, 64, 400) fp32;  num_samples = 48000 (fixed)
//
//  K1: per-j interp-weight prefix tables (shared by all (b,m)), double-accumulated.
//  K2: per-(b,m) 400-knot fp64 recurrence (warp scan), segment base phases stored
//      reduced mod 2pi as fp32, laid out [b][r][m] for coalesced reads in K3.
//  K3: main compute — block per (batch, region); region = head(60) / 399 segments(120) / tail(60).
//      All fp32, polynomial sin (no MUFU).

#define NB 16
#define NM 64
#define NK 400
#define NS 48000
#define NREG 401            // r=0 head, r=1..399 segments k=0..398, r=400 tail(k=399)

__device__ float  g_Wpre[NS];             // within-segment inclusive prefix of t~ (j >= 60)
__device__ double g_Wfull[NK];            // per-segment sum of t~      (k = 0..398 used)
__device__ double g_Ufull[NK];            // per-segment sum of (1-t~)  (k = 0..398 used)
__device__ float  g_Bred[NB * NREG * NM]; // base phase mod 2pi, index (b*NREG + r)*NM + m

__device__ __forceinline__ float reduce2pi(double x) {
    double q = rint(x * 0.15915494309189535);   // 1/(2pi)
    return (float)(x - q * 6.283185307179586);
}

// ---------------- K1: per-j weight tables ----------------
__global__ void k1_tables() {
    int k = blockIdx.x * blockDim.x + threadIdx.x;
    if (k >= 400) return;
    const float SF = (float)(400.0 / 48000.0);
    int len   = (k == 399) ? 60 : 120;
    int jbase = 120 * k + 60;
    double W = 0.0, U = 0.0;
    for (int s = 0; s < len; s++) {
        float jf  = (float)(jbase + s);
        float pos = __fadd_rn(__fmul_rn(__fadd_rn(jf, 0.5f), SF), -0.5f);
        pos = fminf(fmaxf(pos, 0.0f), 399.0f);
        float wt = __fsub_rn(pos, (float)k);
        float u  = __fsub_rn(1.0f, wt);
        W += (double)wt;
        U += (double)u;
        g_Wpre[jbase + s] = (float)W;
    }
    if (k < 399) { g_Wfull[k] = W; g_Ufull[k] = U; }
}

// ---------------- K2: per-(b,m) segment base phases ----------------
// One warp per (b,m). Lane l owns segments [13l, 13l+13) ∩ [0,399).
__global__ void k2_bases(const float* __restrict__ params) {
    int gw   = (blockIdx.x * blockDim.x + threadIdx.x) >> 5;  // 0..1023
    int lane = threadIdx.x & 31;
    int b = gw >> 6, m = gw & 63;

    const float* __restrict__ f = params + (((size_t)b * 3 + 0) * NM + m) * NK;
    float phase0 = params[(((size_t)b * 3 + 2) * NM + m) * NK + 0];

    int kb = lane * 13;
    int ke = min(kb + 13, 399);

    double S = 0.0;
    for (int k = kb; k < ke; k++)
        S += (double)f[k] * g_Ufull[k] + (double)f[k + 1] * g_Wfull[k];

    // inclusive warp scan (doubles)
    double inc = S;
    #pragma unroll
    for (int d = 1; d < 32; d <<= 1) {
        double o = __shfl_up_sync(0xffffffffu, inc, d);
        if (lane >= d) inc += o;
    }
    double excl = inc - S;

    double B = (double)phase0 + 60.0 * (double)f[0] + excl;

    float* __restrict__ Bout = g_Bred + (size_t)b * NREG * NM + m;  // + r*NM
    if (lane == 0) Bout[0] = reduce2pi((double)phase0);             // head base (r=0)

    for (int k = kb; k < ke; k++) {
        Bout[(size_t)(k + 1) * NM] = reduce2pi(B);
        B += (double)f[k] * g_Ufull[k] + (double)f[k + 1] * g_Wfull[k];
    }
    if (kb < 399 && ke == 399)                                      // lane 30: tail base (r=400)
        Bout[(size_t)400 * NM] = reduce2pi(B);
}

// ---------------- K3: main synthesis ----------------
__global__ __launch_bounds__(128) void k3_synth(const float* __restrict__ params,
                                                float* __restrict__ out) {
    const float SF     = (float)(400.0 / 48000.0);
    const float INV_PI = 0.31830988618379067f;
    const float PI_HI  = 3.140625f;
    const float PI_LO  = 9.6765358979323846e-4f;
    const float C3 = -1.6666666666e-1f;
    const float C5 =  8.3333333333e-3f;
    const float C7 = -1.9841269841e-4f;
    const float C9 =  2.7557319224e-6f;

    unsigned bid = blockIdx.x;
    int r = (int)(bid % NREG);
    int b = (int)(bid / NREG);

    __shared__ float4 s_p[NM];   // {f_k0, f_k1, a_k0, a_k1}
    __shared__ float  s_B[NM];

    int k0 = (r == 0) ? 0 : (r - 1);
    int k1 = min(k0 + 1, 399);

    {
        const float* __restrict__ fb = params + ((size_t)b * 3 + 0) * NM * NK;
        const float* __restrict__ ab = params + ((size_t)b * 3 + 1) * NM * NK;
        const float* __restrict__ Bb = g_Bred + ((size_t)b * NREG + r) * NM;
        for (int m = threadIdx.x; m < NM; m += blockDim.x) {
            const float* fm = fb + (size_t)m * NK;
            const float* am = ab + (size_t)m * NK;
            s_p[m] = make_float4(__ldg(fm + k0), __ldg(fm + k1), __ldg(am + k0), __ldg(am + k1));
            s_B[m] = Bb[m];
        }
    }
    __syncthreads();

    int len = (r == 0 || r == 400) ? 60 : 120;
    int s = threadIdx.x;
    if (s >= len) return;

    int j = (r == 0) ? s : (120 * (r - 1) + 60 + s);
    float sp1 = (float)(s + 1);

    float Up, Wp, wt, u;
    if (r == 0) {
        Wp = 0.0f; Up = sp1; wt = 0.0f; u = 1.0f;
    } else {
        float jf  = (float)j;
        float pos = __fadd_rn(__fmul_rn(__fadd_rn(jf, 0.5f), SF), -0.5f);
        pos = fminf(fmaxf(pos, 0.0f), 399.0f);
        wt = __fsub_rn(pos, (float)k0);
        u  = __fsub_rn(1.0f, wt);
        Wp = g_Wpre[j];
        Up = sp1 - Wp;
    }

    float acc = 0.0f;
    #pragma unroll 8
    for (int m = 0; m < NM; m++) {
        float4 p = s_p[m];
        float  B = s_B[m];
        float ph  = fmaf(p.x, Up, fmaf(p.y, Wp, B));
        float amp = fmaf(p.z, u, p.w * wt);
        // sin(ph): reduce by pi, deg-9 odd Taylor on [-pi/2, pi/2]
        int   ki = __float2int_rn(ph * INV_PI);
        float kf = (float)ki;
        float rr = fmaf(kf, -PI_HI, ph);
        rr = fmaf(kf, -PI_LO, rr);
        float r2 = rr * rr;
        float t  = fmaf(r2, C9, C7);
        t = fmaf(r2, t, C5);
        t = fmaf(r2, t, C3);
        float sn = fmaf(r2 * rr, t, rr);
        sn = __int_as_float(__float_as_int(sn) ^ ((ki & 1) << 31));
        acc = fmaf(amp, sn, acc);
    }
    out[(size_t)b * NS + j] = acc;
}

extern "C" void kernel_launch(void* const* d_in, const int* in_sizes, int n_in,
                              void* d_out, int out_size) {
    const float* params = (const float*)d_in[0];
    float* out = (float*)d_out;

    k1_tables<<<1, 400>>>();
    k2_bases<<<256, 128>>>(params);              // 1024 warps, one per (b,m)
    k3_synth<<<NB * NREG, 128>>>(params, out);   // 6416 blocks
}

// round 15
// speedup vs baseline: 2.1372x; 2.1372x over previous
#include <cuda_runtime.h>
#include <cuda_bf16.h>
#include <math.h>

// ModalSynth: y[b,0,j] = sum_m a[b,m,j] * sin( cumsum_j(w[b,m,:]) + phase0[b,m] )
// params: (16, 3, 64, 400) fp32;  num_samples = 48000 (fixed)
//
//  K1: per-j interp-weight prefix tables — one block per segment, block-scan in fp64
//      (R12 fix: old single-block serial version was 72us of the 127us total).
//  K2: per-(b,m) 400-knot fp64 recurrence (warp scan), segment base phases stored
//      reduced mod 2pi as fp32, laid out [b][r][m] for coalesced reads in K3.
//  K3: main compute — block per (batch, region); region = head(60) / 399 segments(120) / tail(60).
//      All fp32, polynomial sin (no MUFU).

#define NB 16
#define NM 64
#define NK 400
#define NS 48000
#define NREG 401            // r=0 head, r=1..399 segments k=0..398, r=400 tail(k=399)

__device__ float  g_Wpre[NS];             // within-segment inclusive prefix of t~ (j >= 60)
__device__ double g_Wfull[NK];            // per-segment sum of t~      (k = 0..398 used)
__device__ double g_Ufull[NK];            // per-segment sum of (1-t~)  (k = 0..398 used)
__device__ float  g_Bred[NB * NREG * NM]; // base phase mod 2pi, index (b*NREG + r)*NM + m

__device__ __forceinline__ float reduce2pi(double x) {
    double q = rint(x * 0.15915494309189535);   // 1/(2pi)
    return (float)(x - q * 6.283185307179586);
}

// ---------------- K1: per-j weight tables (block per segment, fp64 block scan) ----------------
__global__ __launch_bounds__(128) void k1_tables() {
    int k = blockIdx.x;          // segment 0..399
    int s = threadIdx.x;         // sample-in-segment 0..127
    int len   = (k == 399) ? 60 : 120;
    int jbase = 120 * k + 60;

    const float SF = (float)(400.0 / 48000.0);

    __shared__ double sW[128];
    __shared__ double sU[128];

    float wt = 0.0f, u = 0.0f;
    if (s < len) {
        float jf  = (float)(jbase + s);
        float pos = __fadd_rn(__fmul_rn(__fadd_rn(jf, 0.5f), SF), -0.5f);
        pos = fminf(fmaxf(pos, 0.0f), 399.0f);
        wt = __fsub_rn(pos, (float)k);
        u  = __fsub_rn(1.0f, wt);
    }
    sW[s] = (double)wt;          // zeros beyond len
    sU[s] = (double)u;
    __syncthreads();

    // Hillis-Steele inclusive scan over 128 doubles (7 steps)
    #pragma unroll
    for (int d = 1; d < 128; d <<= 1) {
        double w  = (s >= d) ? sW[s - d] : 0.0;
        double uu = (s >= d) ? sU[s - d] : 0.0;
        __syncthreads();
        sW[s] += w;
        sU[s] += uu;
        __syncthreads();
    }

    if (s < len) g_Wpre[jbase + s] = (float)sW[s];
    if (k < 399 && s == len - 1) { g_Wfull[k] = sW[s]; g_Ufull[k] = sU[s]; }
}

// ---------------- K2: per-(b,m) segment base phases ----------------
// One warp per (b,m). Lane l owns segments [13l, 13l+13) ∩ [0,399).
__global__ void k2_bases(const float* __restrict__ params) {
    int gw   = (blockIdx.x * blockDim.x + threadIdx.x) >> 5;  // 0..1023
    int lane = threadIdx.x & 31;
    int b = gw >> 6, m = gw & 63;

    const float* __restrict__ f = params + (((size_t)b * 3 + 0) * NM + m) * NK;
    float phase0 = params[(((size_t)b * 3 + 2) * NM + m) * NK + 0];

    int kb = lane * 13;
    int ke = min(kb + 13, 399);

    double S = 0.0;
    for (int k = kb; k < ke; k++)
        S += (double)f[k] * g_Ufull[k] + (double)f[k + 1] * g_Wfull[k];

    // inclusive warp scan (doubles)
    double inc = S;
    #pragma unroll
    for (int d = 1; d < 32; d <<= 1) {
        double o = __shfl_up_sync(0xffffffffu, inc, d);
        if (lane >= d) inc += o;
    }
    double excl = inc - S;

    double B = (double)phase0 + 60.0 * (double)f[0] + excl;

    float* __restrict__ Bout = g_Bred + (size_t)b * NREG * NM + m;  // + r*NM
    if (lane == 0) Bout[0] = reduce2pi((double)phase0);             // head base (r=0)

    for (int k = kb; k < ke; k++) {
        Bout[(size_t)(k + 1) * NM] = reduce2pi(B);
        B += (double)f[k] * g_Ufull[k] + (double)f[k + 1] * g_Wfull[k];
    }
    if (kb < 399 && ke == 399)                                      // lane 30: tail base (r=400)
        Bout[(size_t)400 * NM] = reduce2pi(B);
}

// ---------------- K3: main synthesis ----------------
__global__ __launch_bounds__(128) void k3_synth(const float* __restrict__ params,
                                                float* __restrict__ out) {
    const float SF     = (float)(400.0 / 48000.0);
    const float INV_PI = 0.31830988618379067f;
    const float PI_HI  = 3.140625f;
    const float PI_LO  = 9.6765358979323846e-4f;
    const float C3 = -1.6666666666e-1f;
    const float C5 =  8.3333333333e-3f;
    const float C7 = -1.9841269841e-4f;
    const float C9 =  2.7557319224e-6f;

    unsigned bid = blockIdx.x;
    int r = (int)(bid % NREG);
    int b = (int)(bid / NREG);

    __shared__ float4 s_p[NM];   // {f_k0, f_k1, a_k0, a_k1}
    __shared__ float  s_B[NM];

    int k0 = (r == 0) ? 0 : (r - 1);
    int k1 = min(k0 + 1, 399);

    {
        const float* __restrict__ fb = params + ((size_t)b * 3 + 0) * NM * NK;
        const float* __restrict__ ab = params + ((size_t)b * 3 + 1) * NM * NK;
        const float* __restrict__ Bb = g_Bred + ((size_t)b * NREG + r) * NM;
        for (int m = threadIdx.x; m < NM; m += blockDim.x) {
            const float* fm = fb + (size_t)m * NK;
            const float* am = ab + (size_t)m * NK;
            s_p[m] = make_float4(__ldg(fm + k0), __ldg(fm + k1), __ldg(am + k0), __ldg(am + k1));
            s_B[m] = Bb[m];
        }
    }
    __syncthreads();

    int len = (r == 0 || r == 400) ? 60 : 120;
    int s = threadIdx.x;
    if (s >= len) return;

    int j = (r == 0) ? s : (120 * (r - 1) + 60 + s);
    float sp1 = (float)(s + 1);

    float Up, Wp, wt, u;
    if (r == 0) {
        Wp = 0.0f; Up = sp1; wt = 0.0f; u = 1.0f;
    } else {
        float jf  = (float)j;
        float pos = __fadd_rn(__fmul_rn(__fadd_rn(jf, 0.5f), SF), -0.5f);
        pos = fminf(fmaxf(pos, 0.0f), 399.0f);
        wt = __fsub_rn(pos, (float)k0);
        u  = __fsub_rn(1.0f, wt);
        Wp = g_Wpre[j];
        Up = sp1 - Wp;
    }

    float acc = 0.0f;
    #pragma unroll 8
    for (int m = 0; m < NM; m++) {
        float4 p = s_p[m];
        float  B = s_B[m];
        float ph  = fmaf(p.x, Up, fmaf(p.y, Wp, B));
        float amp = fmaf(p.z, u, p.w * wt);
        // sin(ph): reduce by pi, deg-9 odd Taylor on [-pi/2, pi/2]
        int   ki = __float2int_rn(ph * INV_PI);
        float kf = (float)ki;
        float rr = fmaf(kf, -PI_HI, ph);
        rr = fmaf(kf, -PI_LO, rr);
        float r2 = rr * rr;
        float t  = fmaf(r2, C9, C7);
        t = fmaf(r2, t, C5);
        t = fmaf(r2, t, C3);
        float sn = fmaf(r2 * rr, t, rr);
        sn = __int_as_float(__float_as_int(sn) ^ ((ki & 1) << 31));
        acc = fmaf(amp, sn, acc);
    }
    out[(size_t)b * NS + j] = acc;
}

extern "C" void kernel_launch(void* const* d_in, const int* in_sizes, int n_in,
                              void* d_out, int out_size) {
    const float* params = (const float*)d_in[0];
    float* out = (float*)d_out;

    k1_tables<<<400, 128>>>();                   // block per segment (was 1x400: 72us serial fp64)
    k2_bases<<<256, 128>>>(params);              // 1024 warps, one per (b,m)
    k3_synth<<<NB * NREG, 128>>>(params, out);   // 6416 blocks
}